// round 16
// baseline (speedup 1.0000x reference)
#include <cuda_runtime.h>
#include <cstdint>

#define BB 2
#define NN 8192
#define CC 80
#define KCAP 128
#define LCAP 16          /* per-victim smem list cap per block */
#define MAXIT 64
#define CELLS 256        /* 16x16 spatial cells */
#define NT (NN/64)       /* 128 tiles per batch */
#define NMSB 32
#define NMST 512

typedef unsigned long long u64;
typedef unsigned int u32;
typedef unsigned short u16;
typedef unsigned char u8;

/* output layout (concatenated flat float32, tuple order) */
#define OFF_BOXES 0
#define OFF_MS    (BB*NN*4)
#define OFF_LB    (OFF_MS + BB*NN)
#define OFF_KEEP  (OFF_LB + BB*NN)
#define OFF_ALL   (OFF_KEEP + BB*NN)

/* static device scratch */
__device__ u32    g_key32[BB][NN];      /* ~score_bits (original order) */
__device__ u8     g_validb[BB][NN];
__device__ u8     g_cell[BB][NN];
__device__ int    g_off[BB][CELLS];
__device__ u16    g_perm[BB][NN];       /* sorted pos -> original idx */
__device__ float4 g_sbox[BB][NN];
__device__ u32    g_skey[BB][NN];
__device__ u8     g_sval[BB][NN];
__device__ u32    g_taabb[BB][NT][4];   /* u32-monotonic AABB (atomics) */
__device__ u8     g_keep[BB * NN];      /* sorted space */
__device__ int    g_cnt[BB][NN];        /* sorted space */
__device__ u16    g_list[BB][NN][KCAP]; /* sorted space */
__device__ int    g_changed[MAXIT];
__device__ u32    g_bar;

/* ------------------------------------------------------------------ */
/* Kernel 1: sigmoid / max / argmax / decode / valid / cell (+init)    */
__global__ void prep_kernel(const float* __restrict__ logits,
                            const float* __restrict__ deltas,
                            const float* __restrict__ anchors,
                            float* __restrict__ out)
{
    int wid  = (blockIdx.x * blockDim.x + threadIdx.x) >> 5;
    int lane = threadIdx.x & 31;
    if (wid >= BB * NN) return;
    int b = wid / NN, n = wid % NN;

    if (lane == 1) g_cnt[b][n] = 0;
    if (wid < MAXIT && lane == 2) g_changed[wid] = 0;
    if (wid == 0 && lane == 3) g_bar = 0u;
    if (wid < BB * NT && lane == 4) {          /* AABB init: min=+max, max=0 */
        u32* ta = &g_taabb[0][0][0] + wid * 4;
        ta[0] = 0x7f7fffffu; ta[1] = 0x7f7fffffu;
        ta[2] = 0u;          ta[3] = 0u;
    }

    const float4* lg4 = (const float4*)(logits + (size_t)wid * CC);
    float4* as4       = (float4*)(out + OFF_ALL + (size_t)wid * CC);

    float mv = -INFINITY; int mi = 0;
    if (lane < 20) {
        float4 v = lg4[lane];
        float4 s;
        s.x = __fdividef(1.0f, 1.0f + __expf(-v.x));
        s.y = __fdividef(1.0f, 1.0f + __expf(-v.y));
        s.z = __fdividef(1.0f, 1.0f + __expf(-v.z));
        s.w = __fdividef(1.0f, 1.0f + __expf(-v.w));
        as4[lane] = s;

        mv = v.x; mi = lane * 4;
        if (v.y > mv) { mv = v.y; mi = lane * 4 + 1; }
        if (v.z > mv) { mv = v.z; mi = lane * 4 + 2; }
        if (v.w > mv) { mv = v.w; mi = lane * 4 + 3; }
    }

    for (int off = 16; off; off >>= 1) {
        float ov = __shfl_down_sync(0xffffffffu, mv, off);
        int   oi = __shfl_down_sync(0xffffffffu, mi, off);
        if (ov > mv || (ov == mv && oi < mi)) { mv = ov; mi = oi; }
    }

    if (lane == 0) {
        float ms = 1.0f / (1.0f + expf(-mv));   /* accurate at threshold */
        out[OFF_MS + wid] = ms;
        out[OFF_LB + wid] = (float)mi;

        const float* dl = deltas  + (size_t)wid * 4;
        const float* an = anchors + (size_t)n * 4;
        float a0 = an[0], a1 = an[1], a2 = an[2], a3 = an[3];
        float aw = a2 - a0, ah = a3 - a1;
        float acx = a0 + 0.5f * aw, acy = a1 + 0.5f * ah;
        float dx = dl[0], dy = dl[1];
        float dw = fminf(dl[2], 4.0f), dh = fminf(dl[3], 4.0f);
        float pcx = dx * aw + acx, pcy = dy * ah + acy;
        float pw = expf(dw) * aw, ph = expf(dh) * ah;
        float x1 = fminf(fmaxf(pcx - 0.5f * pw, 0.0f), 1.0f);
        float y1 = fminf(fmaxf(pcy - 0.5f * ph, 0.0f), 1.0f);
        float x2 = fminf(fmaxf(pcx + 0.5f * pw, 0.0f), 1.0f);
        float y2 = fminf(fmaxf(pcy + 0.5f * ph, 0.0f), 1.0f);

        float* bo = out + OFF_BOXES + (size_t)wid * 4;
        bo[0] = x1; bo[1] = y1; bo[2] = x2; bo[3] = y2;

        float w = x2 - x1, h = y2 - y1;
        u8 valid = (ms > 0.5f) && (w > 0.01f) && (h > 0.01f) &&
                   (w < 0.99f) && (h < 0.99f);
        g_validb[b][n] = valid;
        g_key32[b][n] = ~__float_as_uint(ms);

        int ix = min(15, max(0, (int)((x1 + x2) * 8.0f)));
        int iy = min(15, max(0, (int)((y1 + y2) * 8.0f)));
        g_cell[b][n] = (u8)(ix * 16 + iy);
    }
}

/* ------------------------------------------------------------------ */
/* Kernel 2: per-batch cell histogram (smem) + exclusive prefix        */
__global__ void prefix_kernel()
{
    int b = blockIdx.x;
    int t = threadIdx.x;   /* 256 */
    __shared__ int s[CELLS];
    s[t] = 0;
    __syncthreads();
    for (int i = t; i < NN; i += 256)
        atomicAdd(&s[g_cell[b][i]], 1);
    __syncthreads();
    int my = s[t];
    __syncthreads();
    for (int off = 1; off < CELLS; off <<= 1) {
        int v = (t >= off) ? s[t - off] : 0;
        __syncthreads();
        s[t] += v;
        __syncthreads();
    }
    g_off[b][t] = s[t] - my;   /* exclusive */
}

/* ------------------------------------------------------------------ */
/* Kernel 3: scatter into sorted arrays + tile AABB via u32 atomics    */
__global__ void scatter_kernel(const float* __restrict__ out)
{
    int idx = blockIdx.x * blockDim.x + threadIdx.x;
    if (idx >= BB * NN) return;
    int b = idx / NN, n = idx % NN;

    u8 cell = g_cell[b][n];
    int pos = atomicAdd(&g_off[b][cell], 1);
    g_perm[b][pos] = (u16)n;
    float4 bx = *(const float4*)(out + OFF_BOXES + ((size_t)b * NN + n) * 4);
    g_sbox[b][pos]  = bx;
    g_skey[b][pos]  = g_key32[b][n];
    u8 v = g_validb[b][n];
    g_sval[b][pos]  = v;
    g_keep[b * NN + pos] = v;

    int tile = pos >> 6;
    atomicMin(&g_taabb[b][tile][0], __float_as_uint(bx.x));
    atomicMin(&g_taabb[b][tile][1], __float_as_uint(bx.y));
    atomicMax(&g_taabb[b][tile][2], __float_as_uint(bx.z));
    atomicMax(&g_taabb[b][tile][3], __float_as_uint(bx.w));
}

/* ------------------------------------------------------------------ */
/* Kernel 4: pairs. 256 threads = 1 col tile x 4 row tiles.            */
/* Col-tile smem fill + flush amortized over 4 row tiles.              */
__global__ __launch_bounds__(256)
void pairs_kernel()
{
    int cb  = blockIdx.x;
    int rbg = blockIdx.y;
    int b   = blockIdx.z;
    if (rbg * 4 > cb) return;           /* uniform: whole block above diag */

    int t    = threadIdx.x;             /* 0..255 */
    int sub  = t >> 6;                  /* row-tile subgroup 0..3 */
    int st   = t & 63;                  /* thread within subgroup */
    int lane = t & 31;
    int rb   = rbg * 4 + sub;
    bool subOK = (rb <= cb);

    __shared__ int    s_live;
    __shared__ float4 sbox[64];
    __shared__ u32    skey[64];
    __shared__ u8     sval[64];
    __shared__ u16    spr[64];
    __shared__ u32    lcnt[320];          /* 0..255 row victims, 256..319 col */
    __shared__ u16    llist[320 * LCAP];  /* 10 KB */

    /* col tile AABB (uniform) */
    float cax1 = __uint_as_float(g_taabb[b][cb][0]);
    float cay1 = __uint_as_float(g_taabb[b][cb][1]);
    float cax2 = __uint_as_float(g_taabb[b][cb][2]);
    float cay2 = __uint_as_float(g_taabb[b][cb][3]);

    /* per-subgroup row tile AABB overlap vote */
    bool ov = false;
    if (subOK) {
        float rax1 = __uint_as_float(g_taabb[b][rb][0]);
        float ray1 = __uint_as_float(g_taabb[b][rb][1]);
        float rax2 = __uint_as_float(g_taabb[b][rb][2]);
        float ray2 = __uint_as_float(g_taabb[b][rb][3]);
        ov = (fminf(rax2, cax2) > fmaxf(rax1, cax1) &&
              fminf(ray2, cay2) > fmaxf(ray1, cay1));
    }
    if (t == 0) s_live = 0;
    __syncthreads();
    if (ov && st == 0) s_live = 1;
    __syncthreads();
    if (!s_live) return;                /* uniform exit: no overlap at all */

    /* fill col tile smem (first subgroup) + zero victim counters */
    if (t < 64) {
        int cj = cb * 64 + t;
        sbox[t] = g_sbox[b][cj];
        skey[t] = g_skey[b][cj];
        sval[t] = g_sval[b][cj];
        spr[t]  = g_perm[b][cj];
    }
    for (int s = t; s < 320; s += 256) lcnt[s] = 0;
    __syncthreads();

    if (ov) {
        int i = rb * 64 + st;
        float4 rbx = g_sbox[b][i];
        float ar = (rbx.z - rbx.x) * (rbx.w - rbx.y);
        u32  kr = g_skey[b][i];
        u8   rv = g_sval[b][i];
        u16  rp = g_perm[b][i];

        /* warp AABB over this warp's 32 row boxes */
        float wx1 = rbx.x, wy1 = rbx.y, wx2 = rbx.z, wy2 = rbx.w;
        for (int off = 16; off; off >>= 1) {
            wx1 = fminf(wx1, __shfl_xor_sync(0xffffffffu, wx1, off));
            wy1 = fminf(wy1, __shfl_xor_sync(0xffffffffu, wy1, off));
            wx2 = fmaxf(wx2, __shfl_xor_sync(0xffffffffu, wx2, off));
            wy2 = fmaxf(wy2, __shfl_xor_sync(0xffffffffu, wy2, off));
        }

        /* warp-uniform 64-bit survivor mask over columns */
        u64 mask;
        {
            float4 c0 = sbox[lane];
            float4 c1 = sbox[lane + 32];
            bool s0 = sval[lane] &&
                      fminf(wx2, c0.z) > fmaxf(wx1, c0.x) &&
                      fminf(wy2, c0.w) > fmaxf(wy1, c0.y);
            bool s1 = sval[lane + 32] &&
                      fminf(wx2, c1.z) > fmaxf(wx1, c1.x) &&
                      fminf(wy2, c1.w) > fmaxf(wy1, c1.y);
            mask = (u64)__ballot_sync(0xffffffffu, s0)
                 | ((u64)__ballot_sync(0xffffffffu, s1) << 32);
        }

        /* per-row prune */
        bool active = rv &&
                      fminf(rbx.z, cax2) > fmaxf(rbx.x, cax1) &&
                      fminf(rbx.w, cay2) > fmaxf(rbx.y, cay1);
        if (!active) mask = 0;

        bool diag = (rb == cb);
        u32 rowc = 0;
        while (mask) {
            int j = __ffsll((long long)mask) - 1;
            mask &= mask - 1;
            float4 cx = sbox[j];
            float aj = (cx.z - cx.x) * (cx.w - cx.y);
            float ix1 = fmaxf(rbx.x, cx.x);
            float iy1 = fmaxf(rbx.y, cx.y);
            float ix2 = fminf(rbx.z, cx.z);
            float iy2 = fminf(rbx.w, cx.w);
            float inter = fmaxf(ix2 - ix1, 0.0f) * fmaxf(iy2 - iy1, 0.0f);
            float uni = ar + aj - inter;
            if (inter > 0.5f * fmaxf(uni, 1e-9f) && (!diag || j > st)) {
                u32 kj = skey[j];
                bool jwins = (kj < kr) || (kj == kr && spr[j] < rp);
                if (jwins) {
                    /* victim = my row box; private slot t */
                    if (rowc < LCAP) llist[t * LCAP + rowc] = (u16)(cb * 64 + j);
                    else {
                        int pos = atomicAdd(&g_cnt[b][i], 1);
                        if (pos < KCAP) g_list[b][i][pos] = (u16)(cb * 64 + j);
                    }
                    rowc++;
                } else {
                    /* victim = col box j; shared slot 256+j */
                    u32 p = atomicAdd(&lcnt[256 + j], 1u);
                    if (p < LCAP) llist[(256 + j) * LCAP + p] = (u16)i;
                    else {
                        int pos = atomicAdd(&g_cnt[b][cb * 64 + j], 1);
                        if (pos < KCAP) g_list[b][cb * 64 + j][pos] = (u16)i;
                    }
                }
            }
        }
        lcnt[t] = min(rowc, (u32)LCAP);
    }
    __syncthreads();

    /* bulk flush: one global atomic per non-empty victim slot        */
    /* row slot s -> victim rbg*256 + s; col slot s -> cb*64 + (s-256) */
    for (int s = t; s < 320; s += 256) {
        int c = min((int)lcnt[s], LCAP);
        if (c > 0) {
            int victim = (s < 256) ? (rbg * 256 + s) : (cb * 64 + (s - 256));
            int pos = atomicAdd(&g_cnt[b][victim], c);
            for (int q = 0; q < c && pos + q < KCAP; q++)
                g_list[b][victim][pos + q] = llist[s * LCAP + q];
        }
    }
}

/* ------------------------------------------------------------------ */
/* Kernel 5: NMS fixed point, 32 blocks x 512, dynamic probe loop.     */
__global__ __launch_bounds__(NMST, 1)
void nms_kernel(float* __restrict__ out)
{
    int tid = blockIdx.x * NMST + threadIdx.x;   /* 0 .. 16383 */
    int b = tid >> 13;
    int i = tid & (NN - 1);
    int base = b * NN;

    u8 valid = g_sval[b][i];
    int cnt = valid ? min(g_cnt[b][i], KCAP) : 0;
    const u16* lp = g_list[b][i];

    __shared__ int s_stop;
    __shared__ int s_any;
    u32 tgt = 0;
    u8 cur = valid;

    for (int it = 0; it < MAXIT; it++) {
        if (threadIdx.x == 0) s_any = 0;
        __syncthreads();

        bool ch = false;
        if (cnt > 0) {
#pragma unroll
            for (int rep = 0; rep < 2; rep++) {
                u32 s = 0;
#pragma unroll 4
                for (int q = 0; q < cnt; q++)
                    s |= __ldcg(&g_keep[base + (int)lp[q]]);
                u8 nk = (u8)(s == 0);
                if (nk != cur) { cur = nk; __stcg(&g_keep[base + i], nk); ch = true; }
            }
        }

        u32 w = __ballot_sync(0xffffffffu, ch);
        if ((threadIdx.x & 31) == 0 && w) s_any = 1;
        if (ch) __threadfence();
        __syncthreads();

        tgt += NMSB;
        if (threadIdx.x == 0) {
            if (s_any) atomicExch(&g_changed[it], 1);
            atomicAdd(&g_bar, 1u);
            while (*((volatile u32*)&g_bar) < tgt) { }
            s_stop = (atomicAdd(&g_changed[it], 0) == 0);
        }
        __syncthreads();
        if (s_stop) break;
    }

    out[OFF_KEEP + base + (int)g_perm[b][i]] = (float)cur;
}

/* ------------------------------------------------------------------ */
extern "C" void kernel_launch(void* const* d_in, const int* in_sizes, int n_in,
                              void* d_out, int out_size)
{
    (void)in_sizes; (void)n_in; (void)out_size;
    const float* logits  = (const float*)d_in[0];
    const float* deltas  = (const float*)d_in[1];
    const float* anchors = (const float*)d_in[2];
    float* out = (float*)d_out;

    prep_kernel<<<(BB * NN * 32 + 255) / 256, 256>>>(logits, deltas, anchors, out);
    prefix_kernel<<<BB, CELLS>>>();
    scatter_kernel<<<(BB * NN + 255) / 256, 256>>>(out);
    {
        dim3 g(NT, 32, BB);   /* col tile x row-tile group x batch */
        pairs_kernel<<<g, 256>>>();
    }
    nms_kernel<<<NMSB, NMST>>>(out);
}

// round 17
// speedup vs baseline: 1.0450x; 1.0450x over previous
#include <cuda_runtime.h>
#include <cstdint>

#define BB 2
#define NN 8192
#define CC 80
#define KCAP 128
#define LCAP 16          /* per-victim smem list cap per tile-pair */
#define MAXIT 64
#define CELLS 256        /* 16x16 spatial cells */
#define NT (NN/64)       /* 128 tiles per batch */
#define NMSB 64
#define NMST 256

typedef unsigned long long u64;
typedef unsigned int u32;
typedef unsigned short u16;
typedef unsigned char u8;

/* output layout (concatenated flat float32, tuple order) */
#define OFF_BOXES 0
#define OFF_MS    (BB*NN*4)
#define OFF_LB    (OFF_MS + BB*NN)
#define OFF_KEEP  (OFF_LB + BB*NN)
#define OFF_ALL   (OFF_KEEP + BB*NN)

/* static device scratch */
__device__ u32    g_key32[BB][NN];      /* ~score_bits (original order) */
__device__ u8     g_validb[BB][NN];
__device__ u8     g_cell[BB][NN];
__device__ int    g_off[BB][CELLS];
__device__ u16    g_perm[BB][NN];       /* sorted pos -> original idx */
__device__ float4 g_sbox[BB][NN];
__device__ u32    g_skey[BB][NN];
__device__ u8     g_sval[BB][NN];
__device__ u32    g_taabb[BB][NT][4];   /* u32-monotonic AABB (atomics) */
__device__ u8     g_keep[BB * NN];      /* sorted space */
__device__ int    g_cnt[BB][NN];        /* sorted space */
__device__ u16    g_list[BB][NN][KCAP]; /* sorted space */
__device__ int    g_changed[MAXIT];
__device__ u32    g_bar;

__device__ __forceinline__ float fast_sigmoid(float x)
{
    float th;
    asm("tanh.approx.f32 %0, %1;" : "=f"(th) : "f"(0.5f * x));
    return fmaf(0.5f, th, 0.5f);
}

/* ------------------------------------------------------------------ */
/* Kernel 1: sigmoid / max / argmax / decode / valid / cell (+init)    */
__global__ void prep_kernel(const float* __restrict__ logits,
                            const float* __restrict__ deltas,
                            const float* __restrict__ anchors,
                            float* __restrict__ out)
{
    int wid  = (blockIdx.x * blockDim.x + threadIdx.x) >> 5;
    int lane = threadIdx.x & 31;
    if (wid >= BB * NN) return;
    int b = wid / NN, n = wid % NN;

    if (lane == 1) g_cnt[b][n] = 0;
    if (wid < MAXIT && lane == 2) g_changed[wid] = 0;
    if (wid == 0 && lane == 3) g_bar = 0u;
    if (wid < BB * NT && lane == 4) {          /* AABB init: min=+max, max=0 */
        u32* ta = &g_taabb[0][0][0] + wid * 4;
        ta[0] = 0x7f7fffffu; ta[1] = 0x7f7fffffu;
        ta[2] = 0u;          ta[3] = 0u;
    }

    const float4* lg4 = (const float4*)(logits + (size_t)wid * CC);
    float4* as4       = (float4*)(out + OFF_ALL + (size_t)wid * CC);

    float mv = -INFINITY; int mi = 0;
    if (lane < 20) {
        float4 v = lg4[lane];
        float4 s;
        s.x = fast_sigmoid(v.x);
        s.y = fast_sigmoid(v.y);
        s.z = fast_sigmoid(v.z);
        s.w = fast_sigmoid(v.w);
        as4[lane] = s;

        mv = v.x; mi = lane * 4;
        if (v.y > mv) { mv = v.y; mi = lane * 4 + 1; }
        if (v.z > mv) { mv = v.z; mi = lane * 4 + 2; }
        if (v.w > mv) { mv = v.w; mi = lane * 4 + 3; }
    }

    for (int off = 16; off; off >>= 1) {
        float ov = __shfl_down_sync(0xffffffffu, mv, off);
        int   oi = __shfl_down_sync(0xffffffffu, mi, off);
        if (ov > mv || (ov == mv && oi < mi)) { mv = ov; mi = oi; }
    }

    if (lane == 0) {
        float ms = 1.0f / (1.0f + expf(-mv));   /* exact at threshold */
        out[OFF_MS + wid] = ms;
        out[OFF_LB + wid] = (float)mi;

        const float* dl = deltas  + (size_t)wid * 4;
        const float* an = anchors + (size_t)n * 4;
        float a0 = an[0], a1 = an[1], a2 = an[2], a3 = an[3];
        float aw = a2 - a0, ah = a3 - a1;
        float acx = a0 + 0.5f * aw, acy = a1 + 0.5f * ah;
        float dx = dl[0], dy = dl[1];
        float dw = fminf(dl[2], 4.0f), dh = fminf(dl[3], 4.0f);
        float pcx = dx * aw + acx, pcy = dy * ah + acy;
        float pw = expf(dw) * aw, ph = expf(dh) * ah;
        float x1 = fminf(fmaxf(pcx - 0.5f * pw, 0.0f), 1.0f);
        float y1 = fminf(fmaxf(pcy - 0.5f * ph, 0.0f), 1.0f);
        float x2 = fminf(fmaxf(pcx + 0.5f * pw, 0.0f), 1.0f);
        float y2 = fminf(fmaxf(pcy + 0.5f * ph, 0.0f), 1.0f);

        float* bo = out + OFF_BOXES + (size_t)wid * 4;
        bo[0] = x1; bo[1] = y1; bo[2] = x2; bo[3] = y2;

        float w = x2 - x1, h = y2 - y1;
        u8 valid = (ms > 0.5f) && (w > 0.01f) && (h > 0.01f) &&
                   (w < 0.99f) && (h < 0.99f);
        g_validb[b][n] = valid;
        g_key32[b][n] = ~__float_as_uint(ms);

        int ix = min(15, max(0, (int)((x1 + x2) * 8.0f)));
        int iy = min(15, max(0, (int)((y1 + y2) * 8.0f)));
        g_cell[b][n] = (u8)(ix * 16 + iy);
    }
}

/* ------------------------------------------------------------------ */
/* Kernel 2: per-batch cell histogram (smem) + exclusive prefix        */
__global__ void prefix_kernel()
{
    int b = blockIdx.x;
    int t = threadIdx.x;   /* 256 */
    __shared__ int s[CELLS];
    s[t] = 0;
    __syncthreads();
    for (int i = t; i < NN; i += 256)
        atomicAdd(&s[g_cell[b][i]], 1);
    __syncthreads();
    int my = s[t];
    __syncthreads();
    for (int off = 1; off < CELLS; off <<= 1) {
        int v = (t >= off) ? s[t - off] : 0;
        __syncthreads();
        s[t] += v;
        __syncthreads();
    }
    g_off[b][t] = s[t] - my;   /* exclusive */
}

/* ------------------------------------------------------------------ */
/* Kernel 3: scatter into sorted arrays + tile AABB via u32 atomics    */
__global__ void scatter_kernel(const float* __restrict__ out)
{
    int idx = blockIdx.x * blockDim.x + threadIdx.x;
    if (idx >= BB * NN) return;
    int b = idx / NN, n = idx % NN;

    u8 cell = g_cell[b][n];
    int pos = atomicAdd(&g_off[b][cell], 1);
    g_perm[b][pos] = (u16)n;
    float4 bx = *(const float4*)(out + OFF_BOXES + ((size_t)b * NN + n) * 4);
    g_sbox[b][pos]  = bx;
    g_skey[b][pos]  = g_key32[b][n];
    u8 v = g_validb[b][n];
    g_sval[b][pos]  = v;
    g_keep[b * NN + pos] = v;

    int tile = pos >> 6;
    atomicMin(&g_taabb[b][tile][0], __float_as_uint(bx.x));
    atomicMin(&g_taabb[b][tile][1], __float_as_uint(bx.y));
    atomicMax(&g_taabb[b][tile][2], __float_as_uint(bx.z));
    atomicMax(&g_taabb[b][tile][3], __float_as_uint(bx.w));
}

/* ------------------------------------------------------------------ */
/* Kernel 4: pairs; tile-AABB + per-row + warp column bitmask prunes.  */
__global__ __launch_bounds__(64)
void pairs_kernel()
{
    int b = blockIdx.y;
    int L = blockIdx.x;
    int cb = (int)((sqrtf(8.0f * (float)L + 1.0f) - 1.0f) * 0.5f);
    while ((cb + 1) * (cb + 2) / 2 <= L) cb++;
    while (cb * (cb + 1) / 2 > L) cb--;
    int rb = L - cb * (cb + 1) / 2;     /* rb <= cb */

    float rax1 = __uint_as_float(g_taabb[b][rb][0]);
    float ray1 = __uint_as_float(g_taabb[b][rb][1]);
    float rax2 = __uint_as_float(g_taabb[b][rb][2]);
    float ray2 = __uint_as_float(g_taabb[b][rb][3]);
    float cax1 = __uint_as_float(g_taabb[b][cb][0]);
    float cay1 = __uint_as_float(g_taabb[b][cb][1]);
    float cax2 = __uint_as_float(g_taabb[b][cb][2]);
    float cay2 = __uint_as_float(g_taabb[b][cb][3]);
    if (!(fminf(rax2, cax2) > fmaxf(rax1, cax1) &&
          fminf(ray2, cay2) > fmaxf(ray1, cay1)))
        return;

    int t = threadIdx.x;  /* 64 */
    int lane = t & 31;

    __shared__ float4 sbox[64];
    __shared__ u32    skey[64];
    __shared__ u8     sval[64];
    __shared__ u16    spr[64];
    __shared__ u32    lcnt[128];          /* 0..63 row victims, 64..127 col */
    __shared__ u16    llist[128 * LCAP];  /* 4 KB */

    int cj = cb * 64 + t;
    sbox[t] = g_sbox[b][cj];
    skey[t] = g_skey[b][cj];
    sval[t] = g_sval[b][cj];
    spr[t]  = g_perm[b][cj];
    lcnt[t] = 0; lcnt[t + 64] = 0;
    __syncthreads();

    int i = rb * 64 + t;
    float4 rbx = g_sbox[b][i];
    float ar = (rbx.z - rbx.x) * (rbx.w - rbx.y);
    u32  kr = g_skey[b][i];
    u8   rv = g_sval[b][i];
    u16  rp = g_perm[b][i];

    /* warp AABB over this warp's 32 row boxes */
    float wx1 = rbx.x, wy1 = rbx.y, wx2 = rbx.z, wy2 = rbx.w;
    for (int off = 16; off; off >>= 1) {
        wx1 = fminf(wx1, __shfl_xor_sync(0xffffffffu, wx1, off));
        wy1 = fminf(wy1, __shfl_xor_sync(0xffffffffu, wy1, off));
        wx2 = fmaxf(wx2, __shfl_xor_sync(0xffffffffu, wx2, off));
        wy2 = fmaxf(wy2, __shfl_xor_sync(0xffffffffu, wy2, off));
    }

    /* warp-uniform 64-bit survivor mask over columns */
    u64 mask;
    {
        float4 c0 = sbox[lane];
        float4 c1 = sbox[lane + 32];
        bool s0 = sval[lane] &&
                  fminf(wx2, c0.z) > fmaxf(wx1, c0.x) &&
                  fminf(wy2, c0.w) > fmaxf(wy1, c0.y);
        bool s1 = sval[lane + 32] &&
                  fminf(wx2, c1.z) > fmaxf(wx1, c1.x) &&
                  fminf(wy2, c1.w) > fmaxf(wy1, c1.y);
        mask = (u64)__ballot_sync(0xffffffffu, s0)
             | ((u64)__ballot_sync(0xffffffffu, s1) << 32);
    }

    /* per-row prune: invalid row or row box outside col tile AABB */
    bool active = rv &&
                  fminf(rbx.z, cax2) > fmaxf(rbx.x, cax1) &&
                  fminf(rbx.w, cay2) > fmaxf(rbx.y, cay1);
    if (!active) mask = 0;

    bool diag = (rb == cb);
    u32 rowc = 0;
    while (mask) {
        int j = __ffsll((long long)mask) - 1;
        mask &= mask - 1;
        float4 cx = sbox[j];
        float aj = (cx.z - cx.x) * (cx.w - cx.y);
        float ix1 = fmaxf(rbx.x, cx.x);
        float iy1 = fmaxf(rbx.y, cx.y);
        float ix2 = fminf(rbx.z, cx.z);
        float iy2 = fminf(rbx.w, cx.w);
        float inter = fmaxf(ix2 - ix1, 0.0f) * fmaxf(iy2 - iy1, 0.0f);
        float uni = ar + aj - inter;
        if (inter > 0.5f * fmaxf(uni, 1e-9f) && (!diag || j > t)) {
            u32 kj = skey[j];
            bool jwins = (kj < kr) || (kj == kr && spr[j] < rp);
            if (jwins) {
                if (rowc < LCAP) llist[t * LCAP + rowc] = (u16)(cb * 64 + j);
                else {
                    int pos = atomicAdd(&g_cnt[b][i], 1);
                    if (pos < KCAP) g_list[b][i][pos] = (u16)(cb * 64 + j);
                }
                rowc++;
            } else {
                u32 p = atomicAdd(&lcnt[64 + j], 1u);
                if (p < LCAP) llist[(64 + j) * LCAP + p] = (u16)i;
                else {
                    int pos = atomicAdd(&g_cnt[b][cb * 64 + j], 1);
                    if (pos < KCAP) g_list[b][cb * 64 + j][pos] = (u16)i;
                }
            }
        }
    }
    lcnt[t] = min(rowc, (u32)LCAP);
    __syncthreads();

    /* bulk flush: one global atomic per non-empty victim slot */
#pragma unroll
    for (int s = t; s < 128; s += 64) {
        int c = min((int)lcnt[s], LCAP);
        if (c > 0) {
            int victim = (s < 64) ? (rb * 64 + s) : (cb * 64 + (s - 64));
            int pos = atomicAdd(&g_cnt[b][victim], c);
            for (int q = 0; q < c && pos + q < KCAP; q++)
                g_list[b][victim][pos + q] = llist[s * LCAP + q];
        }
    }
}

/* ------------------------------------------------------------------ */
/* Kernel 5: NMS fixed point, 64 blocks x 256 (LSU spread over 64 SMs) */
__global__ __launch_bounds__(NMST, 1)
void nms_kernel(float* __restrict__ out)
{
    int tid = blockIdx.x * NMST + threadIdx.x;   /* 0 .. 16383 */
    int b = tid >> 13;
    int i = tid & (NN - 1);
    int base = b * NN;

    u8 valid = g_sval[b][i];
    int cnt = valid ? min(g_cnt[b][i], KCAP) : 0;
    const u16* lp = g_list[b][i];

    __shared__ int s_stop;
    __shared__ int s_any;
    u32 tgt = 0;
    u8 cur = valid;

    for (int it = 0; it < MAXIT; it++) {
        if (threadIdx.x == 0) s_any = 0;
        __syncthreads();

        bool ch = false;
        if (cnt > 0) {
#pragma unroll
            for (int rep = 0; rep < 2; rep++) {
                u32 s = 0;
#pragma unroll 4
                for (int q = 0; q < cnt; q++)
                    s |= __ldcg(&g_keep[base + (int)lp[q]]);
                u8 nk = (u8)(s == 0);
                if (nk != cur) { cur = nk; __stcg(&g_keep[base + i], nk); ch = true; }
            }
        }

        u32 w = __ballot_sync(0xffffffffu, ch);
        if ((threadIdx.x & 31) == 0 && w) s_any = 1;
        if (ch) __threadfence();
        __syncthreads();

        tgt += NMSB;
        if (threadIdx.x == 0) {
            if (s_any) atomicExch(&g_changed[it], 1);
            atomicAdd(&g_bar, 1u);
            while (*((volatile u32*)&g_bar) < tgt) { }
            s_stop = (atomicAdd(&g_changed[it], 0) == 0);
        }
        __syncthreads();
        if (s_stop) break;
    }

    out[OFF_KEEP + base + (int)g_perm[b][i]] = (float)cur;
}

/* ------------------------------------------------------------------ */
extern "C" void kernel_launch(void* const* d_in, const int* in_sizes, int n_in,
                              void* d_out, int out_size)
{
    (void)in_sizes; (void)n_in; (void)out_size;
    const float* logits  = (const float*)d_in[0];
    const float* deltas  = (const float*)d_in[1];
    const float* anchors = (const float*)d_in[2];
    float* out = (float*)d_out;

    prep_kernel<<<(BB * NN * 32 + 255) / 256, 256>>>(logits, deltas, anchors, out);
    prefix_kernel<<<BB, CELLS>>>();
    scatter_kernel<<<(BB * NN + 255) / 256, 256>>>(out);
    {
        dim3 g(NT * (NT + 1) / 2, BB);
        pairs_kernel<<<g, 64>>>();
    }
    nms_kernel<<<NMSB, NMST>>>(out);
}